// round 16
// baseline (speedup 1.0000x reference)
#include <cuda_runtime.h>
#include <math.h>

// Problem shape is fixed: N = 16384.
#define N_ELEM 16384
#define NBINS  8192
#define NMOM   7            // m = 0, 1, 3, 5, 7, 9, 11
#define MTHR   1024         // threads for the wide kernels
#define EPT    (N_ELEM / MTHR)  // 16 sorted elements per thread in k_moments
#define PI_D   3.141592653589793

typedef unsigned int uint;

// Scratch (no cudaMalloc allowed). Everything is rewritten every launch:
// g_bins zeroed by k_zero; g_ts/g_us fully overwritten by k_scatter;
// g_Mo overwritten by k_moments. Graph-replay safe.
__device__ uint   g_bins[NBINS];
__device__ float  g_ts[N_ELEM];
__device__ float  g_us[N_ELEM];
__device__ double g_Mo[NMOM];

// ---------------------------------------------------------------------------
// K1: zero the histogram bins.
__global__ void k_zero() {
    const int i = blockIdx.x * MTHR + threadIdx.x;
    if (i < NBINS) g_bins[i] = 0u;
}

// K2: histogram of t into NBINS uniform bins on [0,1).
__global__ void k_hist(const float* __restrict__ yt) {
    const int i = blockIdx.x * MTHR + threadIdx.x;
    float t = yt[i];
    int b = (int)(t * (float)NBINS);
    b = b < 0 ? 0 : (b >= NBINS ? NBINS - 1 : b);
    atomicAdd(&g_bins[b], 1u);
}

// K3: exclusive prefix scan over bins (in place: counts -> start offsets).
__global__ void k_scan() {
    __shared__ uint swtot[8];
    const int tid  = threadIdx.x;          // 256 threads
    const int lane = tid & 31;
    const int wid  = tid >> 5;
    const int base = tid * (NBINS / 256);  // 32 bins per thread

    uint s = 0;
    for (int i = 0; i < NBINS / 256; i++) s += g_bins[base + i];

    uint inc = s;
    #pragma unroll
    for (int o = 1; o < 32; o <<= 1) {
        uint n = __shfl_up_sync(0xFFFFFFFFu, inc, o);
        if (lane >= o) inc += n;
    }
    if (lane == 31) swtot[wid] = inc;
    __syncthreads();
    uint woff = 0;
    for (int w = 0; w < wid; w++) woff += swtot[w];
    uint run = woff + inc - s;             // exclusive offset for this thread

    for (int i = 0; i < NBINS / 256; i++) {
        uint c = g_bins[base + i];
        g_bins[base + i] = run;            // bin start cursor
        run += c;
    }
}

// K4: scatter (t, u) into t-sorted bin order. u = clamp(p, -2, 2) / 2.
__global__ void k_scatter(const float* __restrict__ yt,
                          const float* __restrict__ yp) {
    const int i = blockIdx.x * MTHR + threadIdx.x;
    const float t = yt[i];
    const float p = yp[i];
    int b = (int)(t * (float)NBINS);
    b = b < 0 ? 0 : (b >= NBINS ? NBINS - 1 : b);
    const uint pos = atomicAdd(&g_bins[b], 1u);
    g_ts[pos] = t;
    g_us[pos] = 0.5f * fminf(2.0f, fmaxf(-2.0f, p));
}

// ---------------------------------------------------------------------------
// Block-wide exclusive scan of a double (1024 threads = 32 warps).
__device__ __forceinline__ double block_excl_scan(double v, int lane, int wid,
                                                  double* wtot /* [32] smem */) {
    __syncthreads();                       // protect wtot between calls
    double inc = v;
    #pragma unroll
    for (int o = 1; o < 32; o <<= 1) {
        double n = __shfl_up_sync(0xFFFFFFFFu, inc, o);
        if (lane >= o) inc += n;
    }
    if (lane == 31) wtot[wid] = inc;
    __syncthreads();
    if (wid == 0) {
        double w  = wtot[lane];
        double wi = w;
        #pragma unroll
        for (int o = 1; o < 32; o <<= 1) {
            double n = __shfl_up_sync(0xFFFFFFFFu, wi, o);
            if (lane >= o) wi += n;
        }
        wtot[lane] = wi - w;               // exclusive warp offsets
    }
    __syncthreads();
    return wtot[wid] + inc - v;
}

// K5: one block per moment m in {0,1,3,5,7,9,11}:
//   Mo_m = sum_{i != j} u_i^m u_j^m |t_i - t_j|
//        = 2 * sum_q a_q * ( t_q * S_{<q} - ST_{<q} )     (t-sorted order)
// where a = u^m, S = prefix sum of a, ST = prefix sum of a*t. All f64.
__global__ __launch_bounds__(MTHR) void k_moments() {
    __shared__ double wtot[32];
    __shared__ double sred[32];

    const int tid  = threadIdx.x;
    const int lane = tid & 31;
    const int wid  = tid >> 5;
    const int m    = (blockIdx.x == 0) ? 0 : (2 * (int)blockIdx.x - 1);
    const int base = tid * EPT;

    // Pass 1: local sums of a and a*t over this thread's 16 sorted elements.
    double sa = 0.0, sat = 0.0;
    for (int e = 0; e < EPT; e++) {
        const double t = (double)g_ts[base + e];
        const double u = (double)g_us[base + e];
        double a = 1.0;
        for (int q = 0; q < m; q++) a *= u;
        sa  += a;
        sat += a * t;
    }

    // Exclusive prefixes across the block.
    double S  = block_excl_scan(sa,  lane, wid, wtot);
    double ST = block_excl_scan(sat, lane, wid, wtot);

    // Pass 2: accumulate contributions in sorted order.
    double acc = 0.0;
    for (int e = 0; e < EPT; e++) {
        const double t = (double)g_ts[base + e];
        const double u = (double)g_us[base + e];
        double a = 1.0;
        for (int q = 0; q < m; q++) a *= u;
        acc += a * (t * S - ST);
        S  += a;
        ST += a * t;
    }

    // Block reduce acc.
    #pragma unroll
    for (int o = 16; o > 0; o >>= 1)
        acc += __shfl_xor_sync(0xFFFFFFFFu, acc, o);
    if (lane == 0) sred[wid] = acc;
    __syncthreads();
    if (tid == 0) {
        double tot = 0.0;
        for (int w = 0; w < 32; w++) tot += sred[w];
        g_Mo[blockIdx.x] = 2.0 * tot;      // ordered-pair sum
    }
}

// K6: fit tanh(2w) on [-1,1] with odd Chebyshev (deg 11) via 64-node DCT,
// convert to monomial coefficients, combine with moments, write output.
__global__ void k_final(float* __restrict__ out) {
    __shared__ double sf[64];
    __shared__ double sb[6];

    const int tid = threadIdx.x;           // 64 threads
    const double th = PI_D * ((double)tid + 0.5) / 64.0;
    sf[tid] = tanh(2.0 * cos(th));
    __syncthreads();

    if (tid < 32) {
        const double th1 = PI_D * ((double)tid + 0.5) / 64.0;
        const double th2 = PI_D * ((double)tid + 32.5) / 64.0;
        const double f1 = sf[tid], f2 = sf[tid + 32];
        for (int kk = 0; kk < 6; kk++) {
            const int k = 2 * kk + 1;
            double s = f1 * cos((double)k * th1) + f2 * cos((double)k * th2);
            #pragma unroll
            for (int o = 16; o > 0; o >>= 1)
                s += __shfl_xor_sync(0xFFFFFFFFu, s, o);
            if (tid == 0) sb[kk] = s * (2.0 / 64.0);
        }
    }
    __syncthreads();

    if (tid == 0) {
        // Build monomial coefficients of sum_k b_k T_k(w), odd k = 1..11.
        double Tm1[12], T0[12], mono[12];
        for (int d = 0; d < 12; d++) { Tm1[d] = 0.0; T0[d] = 0.0; mono[d] = 0.0; }
        Tm1[0] = 1.0;                      // T_0
        T0[1]  = 1.0;                      // T_1
        mono[1] += sb[0];                  // b_1 * T_1
        for (int k = 2; k <= 11; k++) {
            double Tn[12];
            for (int d = 0; d < 12; d++) {
                double v = -Tm1[d];
                if (d >= 1) v += 2.0 * T0[d - 1];
                Tn[d] = v;
            }
            if (k & 1) {
                const int kk = (k - 1) / 2;
                for (int d = 0; d <= k; d++) mono[d] += sb[kk] * Tn[d];
            }
            for (int d = 0; d < 12; d++) { Tm1[d] = T0[d]; T0[d] = Tn[d]; }
        }
        // A = sum_{odd m} gamma_m * Mo_m ; total = Mo_0 + A ; cost = -total/(4N^2)
        const double A = mono[1] * g_Mo[1] + mono[3]  * g_Mo[2]
                       + mono[5] * g_Mo[3] + mono[7]  * g_Mo[4]
                       + mono[9] * g_Mo[5] + mono[11] * g_Mo[6];
        const double tot = g_Mo[0] + A;
        const double n2 = (double)N_ELEM * (double)N_ELEM;
        out[0] = (float)(-0.25 * tot / n2);
    }
}

// ---------------------------------------------------------------------------
extern "C" void kernel_launch(void* const* d_in, const int* in_sizes, int n_in,
                              void* d_out, int out_size)
{
    const float* yt = (const float*)d_in[0];  // y_true
    const float* yp = (const float*)d_in[1];  // y_pred
    float* out = (float*)d_out;

    k_zero   <<<(NBINS + MTHR - 1) / MTHR, MTHR>>>();
    k_hist   <<<N_ELEM / MTHR, MTHR>>>(yt);
    k_scan   <<<1, 256>>>();
    k_scatter<<<N_ELEM / MTHR, MTHR>>>(yt, yp);
    k_moments<<<NMOM, MTHR>>>();
    k_final  <<<1, 64>>>(out);
}

// round 17
// speedup vs baseline: 1.6087x; 1.6087x over previous
#include <cuda_runtime.h>
#include <math.h>

// Problem shape is fixed: N = 16384.
#define N_ELEM 16384
#define NBINS  8192
#define THR    1024
#define EPT    (N_ELEM / THR)   // 16 sorted elements per thread
#define PI_D   3.141592653589793

typedef unsigned int uint;

// Global scratch for the t-sorted (t, u) arrays (no cudaMalloc allowed).
// Fully rewritten every launch -> graph-replay safe.
__device__ float g_ts[N_ELEM];
__device__ float g_us[N_ELEM];

// Block-wide exclusive scan of a double (1024 threads = 32 warps).
__device__ __forceinline__ double blk_scan_d(double v, int lane, int wid,
                                             double* wtot /* [32] smem */) {
    __syncthreads();                       // protect wtot between calls
    double inc = v;
    #pragma unroll
    for (int o = 1; o < 32; o <<= 1) {
        double n = __shfl_up_sync(0xFFFFFFFFu, inc, o);
        if (lane >= o) inc += n;
    }
    if (lane == 31) wtot[wid] = inc;
    __syncthreads();
    if (wid == 0) {
        double w  = wtot[lane];
        double wi = w;
        #pragma unroll
        for (int o = 1; o < 32; o <<= 1) {
            double n = __shfl_up_sync(0xFFFFFFFFu, wi, o);
            if (lane >= o) wi += n;
        }
        wtot[lane] = wi - w;               // exclusive warp offsets
    }
    __syncthreads();
    return wtot[wid] + inc - v;
}

// Single fused kernel. Phases (all separated by __syncthreads, one block):
//  1. smem histogram of t into 8192 bins
//  2. exclusive scan of bins (bin cursors)
//  3. counting-sort scatter of (t, u=clamp(p,+-2)/2) to global scratch
//  4. moments Mo_m = sum_{i!=j} u_i^m u_j^m |t_i - t_j|, m in {0,1,3,5,7,9,11}
//     via sorted-prefix identity: Mo_m = 2 * sum_q a_q (t_q S_<q - ST_<q)
//  5. on-device odd-Chebyshev (deg 11) fit of tanh(2w) via 64-node DCT
//  6. combine: S_pairs = (Mo_0 + sum_odd gamma_m Mo_m) / 4 ; out = -S/N^2
__global__ __launch_bounds__(THR) void auc_fused_kernel(
    const float* __restrict__ yt, const float* __restrict__ yp,
    float* __restrict__ out)
{
    __shared__ uint   bins[NBINS];         // 32 KB
    __shared__ double wtot[32];
    __shared__ double sred[32];
    __shared__ double smo[7];
    __shared__ double sf64[64];
    __shared__ double sb[6];

    const int tid  = threadIdx.x;
    const int lane = tid & 31;
    const int wid  = tid >> 5;

    // ---- Phase 1: zero + histogram ----------------------------------------
    #pragma unroll
    for (int i = 0; i < NBINS / THR; i++) bins[tid + i * THR] = 0u;
    __syncthreads();
    #pragma unroll
    for (int i = 0; i < EPT; i++) {
        const float t = yt[tid + i * THR];
        int b = (int)(t * (float)NBINS);
        b = b < 0 ? 0 : (b >= NBINS ? NBINS - 1 : b);
        atomicAdd(&bins[b], 1u);
    }
    __syncthreads();

    // ---- Phase 2: exclusive scan over bins (8 contiguous bins per thread) -
    const int bbase = tid * (NBINS / THR);
    uint bsum = 0;
    #pragma unroll
    for (int i = 0; i < NBINS / THR; i++) bsum += bins[bbase + i];
    {   // block exclusive scan of bsum (uint)
        uint inc = bsum;
        #pragma unroll
        for (int o = 1; o < 32; o <<= 1) {
            uint n = __shfl_up_sync(0xFFFFFFFFu, inc, o);
            if (lane >= o) inc += n;
        }
        if (lane == 31) wtot[wid] = (double)inc;   // reuse wtot as scratch
        __syncthreads();
        uint woff = 0;
        for (int w = 0; w < wid; w++) woff += (uint)wtot[w];
        uint run = woff + inc - bsum;
        #pragma unroll
        for (int i = 0; i < NBINS / THR; i++) {
            uint c = bins[bbase + i];
            bins[bbase + i] = run;                 // bin start cursor
            run += c;
        }
    }
    __syncthreads();

    // ---- Phase 3: scatter into t-sorted bin order --------------------------
    #pragma unroll
    for (int i = 0; i < EPT; i++) {
        const int idx = tid + i * THR;
        const float t = yt[idx];
        const float p = yp[idx];
        int b = (int)(t * (float)NBINS);
        b = b < 0 ? 0 : (b >= NBINS ? NBINS - 1 : b);
        const uint pos = atomicAdd(&bins[b], 1u);
        g_ts[pos] = t;
        g_us[pos] = 0.5f * fminf(2.0f, fmaxf(-2.0f, p));
    }
    __syncthreads();   // intra-block ordering of global writes -> reads

    // ---- Phase 4: moments ---------------------------------------------------
    const int base = tid * EPT;
    float sa[7], sat[7];
    #pragma unroll
    for (int m = 0; m < 7; m++) { sa[m] = 0.f; sat[m] = 0.f; }

    // Pass 1: local sums (f32; <=16 terms, exact enough).
    #pragma unroll
    for (int e = 0; e < EPT; e++) {
        const float t = g_ts[base + e];
        const float u = g_us[base + e];
        const float u2 = u * u;
        sa[0]  += 1.0f;
        sat[0] += t;
        float am = u;
        #pragma unroll
        for (int m = 1; m < 7; m++) {
            sa[m]  += am;
            sat[m] += am * t;
            am *= u2;
        }
    }

    // Exclusive block prefixes (f64 scans -> f32 running state).
    float S[7], ST[7];
    #pragma unroll
    for (int m = 0; m < 7; m++) {
        S[m]  = (float)blk_scan_d((double)sa[m],  lane, wid, wtot);
        ST[m] = (float)blk_scan_d((double)sat[m], lane, wid, wtot);
    }

    // Pass 2: accumulate a_q * (t_q * S_<q - ST_<q) in sorted order.
    float acc[7];
    #pragma unroll
    for (int m = 0; m < 7; m++) acc[m] = 0.f;
    #pragma unroll
    for (int e = 0; e < EPT; e++) {
        const float t = g_ts[base + e];
        const float u = g_us[base + e];
        const float u2 = u * u;
        acc[0] += t * S[0] - ST[0];
        S[0]  += 1.0f;
        ST[0] += t;
        float am = u;
        #pragma unroll
        for (int m = 1; m < 7; m++) {
            acc[m] += am * (t * S[m] - ST[m]);
            S[m]  += am;
            ST[m] += am * t;
            am *= u2;
        }
    }

    // Block-reduce the 7 accumulators (f64, fixed order -> deterministic).
    for (int m = 0; m < 7; m++) {
        double a = (double)acc[m];
        #pragma unroll
        for (int o = 16; o > 0; o >>= 1)
            a += __shfl_xor_sync(0xFFFFFFFFu, a, o);
        if (lane == 0) sred[wid] = a;
        __syncthreads();
        if (tid == 0) {
            double tot = 0.0;
            for (int w = 0; w < 32; w++) tot += sred[w];
            smo[m] = 2.0 * tot;            // ordered-pair moment
        }
        __syncthreads();
    }

    // ---- Phase 5: odd Chebyshev fit of tanh(2w), 64-node DCT ---------------
    if (tid < 64) {
        const double th = PI_D * ((double)tid + 0.5) / 64.0;
        sf64[tid] = tanh(2.0 * cos(th));
    }
    __syncthreads();
    if (tid < 32) {
        const double th1 = PI_D * ((double)tid + 0.5) / 64.0;
        const double th2 = PI_D * ((double)tid + 32.5) / 64.0;
        const double f1 = sf64[tid], f2 = sf64[tid + 32];
        for (int kk = 0; kk < 6; kk++) {
            const int kc = 2 * kk + 1;
            double s = f1 * cos((double)kc * th1) + f2 * cos((double)kc * th2);
            #pragma unroll
            for (int o = 16; o > 0; o >>= 1)
                s += __shfl_xor_sync(0xFFFFFFFFu, s, o);
            if (tid == 0) sb[kk] = s * (2.0 / 64.0);
        }
    }
    __syncthreads();

    // ---- Phase 6: combine and write ----------------------------------------
    if (tid == 0) {
        // Monomial coefficients of sum_k b_k T_k(w), odd k = 1..11.
        double Tm1[12], T0[12], mono[12];
        for (int d = 0; d < 12; d++) { Tm1[d] = 0.0; T0[d] = 0.0; mono[d] = 0.0; }
        Tm1[0] = 1.0;                      // T_0
        T0[1]  = 1.0;                      // T_1
        mono[1] += sb[0];
        for (int kc = 2; kc <= 11; kc++) {
            double Tn[12];
            for (int d = 0; d < 12; d++) {
                double v = -Tm1[d];
                if (d >= 1) v += 2.0 * T0[d - 1];
                Tn[d] = v;
            }
            if (kc & 1) {
                const int kk = (kc - 1) / 2;
                for (int d = 0; d <= kc; d++) mono[d] += sb[kk] * Tn[d];
            }
            for (int d = 0; d < 12; d++) { Tm1[d] = T0[d]; T0[d] = Tn[d]; }
        }
        const double A = mono[1] * smo[1] + mono[3]  * smo[2]
                       + mono[5] * smo[3] + mono[7]  * smo[4]
                       + mono[9] * smo[5] + mono[11] * smo[6];
        const double tot = smo[0] + A;
        const double n2 = (double)N_ELEM * (double)N_ELEM;
        out[0] = (float)(-0.25 * tot / n2);
    }
}

extern "C" void kernel_launch(void* const* d_in, const int* in_sizes, int n_in,
                              void* d_out, int out_size)
{
    const float* yt = (const float*)d_in[0];  // y_true
    const float* yp = (const float*)d_in[1];  // y_pred
    float* out = (float*)d_out;

    auc_fused_kernel<<<1, THR>>>(yt, yp, out);
}